// round 16
// baseline (speedup 1.0000x reference)
#include <cuda_runtime.h>
#include <math.h>

// Problem constants
#define NB   8
#define LL   2048
#define DD   1024
#define HH   512
#define NN   64
#define KSZ  4
#define TOT  (NB*LL*DD)   // 16,777,216 elements = 64 MiB fp32

// -------- device scratch (no runtime allocation allowed) --------
static __device__ float  d_bufA[TOT];   // g_act (B,L,D); later reused as y_t (B,D,L)
static __device__ float  d_bufB[TOT];   // u (B,L,D)
static __device__ float  d_bufC[TOT];   // u_t (B,D,L)
static __device__ float4 d_par[HH*NN];  // (a_re, a_im, w_re, w_im) per (h,n)

// -------- packed f32x2 helpers (FFMA2 path, PTX-only on sm_103a) --------
__device__ __forceinline__ unsigned long long pack2(float lo, float hi) {
    unsigned long long r;
    asm("mov.b64 %0, {%1, %2};" : "=l"(r) : "f"(lo), "f"(hi));
    return r;
}
__device__ __forceinline__ void fma2(unsigned long long& d,
                                     unsigned long long a,
                                     unsigned long long b) {
    asm("fma.rn.f32x2 %0, %1, %2, %0;" : "+l"(d) : "l"(a), "l"(b));
}
__device__ __forceinline__ float lo32(unsigned long long v) {
    return __uint_as_float((unsigned)(v & 0xffffffffull));
}
__device__ __forceinline__ float hi32(unsigned long long v) {
    return __uint_as_float((unsigned)(v >> 32));
}

// ======================= 0) SSM parameter precompute =======================
// A = -exp(log_decay) + i*freq ; step multiplier a = exp(A) ; w = w_re + i*w_im
__global__ void k_params(const float* __restrict__ logd,
                         const float* __restrict__ freq,
                         const float* __restrict__ wre,
                         const float* __restrict__ wim) {
    int i = blockIdx.x * blockDim.x + threadIdx.x;
    if (i >= HH * NN) return;
    float mag = expf(-expf(logd[i]));   // |a| = exp(-exp(log_decay)) < 1
    float s, c;
    sincosf(freq[i], &s, &c);
    d_par[i] = make_float4(mag * c, mag * s, wre[i], wim[i]);
}

// ======================= 1) depthwise circular conv + SiLU =======================
// pad: pb=1, pa=2 (CIRCULAR). out[b,l,d] = silu( sum_k g[b,(l+k-1)%L,d]*ker[k,0,d] + bias[d] )
__global__ void k_conv(const float* __restrict__ g,
                       const float* __restrict__ ker,
                       const float* __restrict__ bias) {
    int idx = blockIdx.x * blockDim.x + threadIdx.x;
    if (idx >= TOT) return;
    int d = idx & (DD - 1);
    int l = (idx >> 10) & (LL - 1);
    int b = idx >> 21;
    const float* gb = g + (size_t)b * LL * DD;
    float acc = bias[d];
#pragma unroll
    for (int k = 0; k < KSZ; k++) {
        int ll = (l + k - 1 + LL) & (LL - 1);
        acc += gb[(size_t)ll * DD + d] * ker[k * DD + d];
    }
    float sg = 1.0f / (1.0f + expf(-acc));   // silu = x * sigmoid(x)
    d_bufA[idx] = acc * sg;
}

// ======================= 2) GEMM1: u = (X @ Win) * g_act =======================
// X: (16384,1024) row-major ; Win: (1024,1024) row-major ; out -> d_bufB (B,L,D)
__global__ __launch_bounds__(256) void k_gemm1(const float* __restrict__ X,
                                               const float* __restrict__ W) {
    __shared__ float As[8][128];
    __shared__ float Bs[8][128];
    const int K = DD;
    int tid = threadIdx.x;
    int m0 = blockIdx.y * 128;
    int n0 = blockIdx.x * 128;

    int a_m = tid >> 1;            // 0..127
    int a_k = (tid & 1) * 4;       // 0 or 4
    int b_k = tid >> 5;            // 0..7
    int b_n = (tid & 31) * 4;      // 0..124

    const float* Ap = X + (size_t)(m0 + a_m) * K + a_k;
    const float* Bp = W + (size_t)b_k * DD + n0 + b_n;

    int tmb = (tid >> 4) * 8;      // row offset within tile
    int tnb = (tid & 15) * 8;      // col offset within tile

    unsigned long long acc[8][4];
#pragma unroll
    for (int i = 0; i < 8; i++)
#pragma unroll
        for (int j = 0; j < 4; j++) acc[i][j] = 0ull;

    float4 av = *(const float4*)Ap;
    float4 bv = *(const float4*)Bp;

    for (int kt = 0; kt < K; kt += 8) {
        __syncthreads();
        As[a_k + 0][a_m] = av.x;
        As[a_k + 1][a_m] = av.y;
        As[a_k + 2][a_m] = av.z;
        As[a_k + 3][a_m] = av.w;
        *(float4*)&Bs[b_k][b_n] = bv;
        __syncthreads();
        if (kt + 8 < K) {
            av = *(const float4*)(Ap + kt + 8);
            bv = *(const float4*)(Bp + (size_t)(kt + 8) * DD);
        }
#pragma unroll
        for (int kk = 0; kk < 8; kk++) {
            float4 x0 = *(const float4*)&As[kk][tmb];
            float4 x1 = *(const float4*)&As[kk][tmb + 4];
            float4 y0 = *(const float4*)&Bs[kk][tnb];
            float4 y1 = *(const float4*)&Bs[kk][tnb + 4];
            unsigned long long bp0 = pack2(y0.x, y0.y);
            unsigned long long bp1 = pack2(y0.z, y0.w);
            unsigned long long bp2 = pack2(y1.x, y1.y);
            unsigned long long bp3 = pack2(y1.z, y1.w);
            float aa[8] = {x0.x, x0.y, x0.z, x0.w, x1.x, x1.y, x1.z, x1.w};
#pragma unroll
            for (int i = 0; i < 8; i++) {
                unsigned long long ad = pack2(aa[i], aa[i]);
                fma2(acc[i][0], ad, bp0);
                fma2(acc[i][1], ad, bp1);
                fma2(acc[i][2], ad, bp2);
                fma2(acc[i][3], ad, bp3);
            }
        }
    }
    // epilogue: multiply by gate, write u
#pragma unroll
    for (int i = 0; i < 8; i++) {
        size_t off = (size_t)(m0 + tmb + i) * DD + n0 + tnb;
        float4 g0 = *(const float4*)&d_bufA[off];
        float4 g1 = *(const float4*)&d_bufA[off + 4];
        float4 o0, o1;
        o0.x = lo32(acc[i][0]) * g0.x;  o0.y = hi32(acc[i][0]) * g0.y;
        o0.z = lo32(acc[i][1]) * g0.z;  o0.w = hi32(acc[i][1]) * g0.w;
        o1.x = lo32(acc[i][2]) * g1.x;  o1.y = hi32(acc[i][2]) * g1.y;
        o1.z = lo32(acc[i][3]) * g1.z;  o1.w = hi32(acc[i][3]) * g1.w;
        *(float4*)&d_bufB[off]     = o0;
        *(float4*)&d_bufB[off + 4] = o1;
    }
}

// ======================= 3) transpose u: (B,L,D) -> (B,D,L) =======================
__global__ void k_transpose() {
    __shared__ float tile[32][33];
    int b  = blockIdx.z;
    int l0 = blockIdx.y * 32;
    int d0 = blockIdx.x * 32;
    int tx = threadIdx.x, ty = threadIdx.y;       // block (32,8)
    const float* src = d_bufB + (size_t)b * LL * DD;
    float*       dst = d_bufC + (size_t)b * LL * DD;
#pragma unroll
    for (int i = 0; i < 32; i += 8)
        tile[ty + i][tx] = src[(size_t)(l0 + ty + i) * DD + d0 + tx];
    __syncthreads();
#pragma unroll
    for (int i = 0; i < 32; i += 8)
        dst[(size_t)(d0 + ty + i) * LL + l0 + tx] = tile[tx][ty + i];
}

// ======================= 4) complex diagonal SSM scan =======================
// One warp per (b,h). Lane owns states n=lane and n=lane+32.
// S[l] = a*S[l-1] + u[l];  y[l] = sum_n w_n * S_n[l]  (exactly equals FFT conv)
__global__ __launch_bounds__(256) void k_scan() {
    int warp = (blockIdx.x * blockDim.x + threadIdx.x) >> 5;   // 0..4095
    int lane = threadIdx.x & 31;
    int b = warp >> 9;        // /512
    int h = warp & 511;

    const float* ure = d_bufC + ((size_t)b * DD + h) * LL;
    const float* uim = ure + (size_t)HH * LL;
    float* yre = d_bufA + ((size_t)b * DD + h) * LL;
    float* yim = yre + (size_t)HH * LL;

    float4 p0 = d_par[h * NN + lane];
    float4 p1 = d_par[h * NN + lane + 32];
    float a0r = p0.x, a0i = p0.y, w0r = p0.z, w0i = p0.w;
    float a1r = p1.x, a1i = p1.y, w1r = p1.z, w1i = p1.w;
    float na0i = -a0i, na1i = -a1i, nw0i = -w0i, nw1i = -w1i;

    float s0r = 0.f, s0i = 0.f, s1r = 0.f, s1i = 0.f;

    for (int l0 = 0; l0 < LL; l0 += 32) {
        float urv = ure[l0 + lane];
        float uiv = uim[l0 + lane];
        float kr = 0.f, ki = 0.f;
#pragma unroll
        for (int t = 0; t < 32; t++) {
            float ur = __shfl_sync(0xffffffffu, urv, t);
            float ui = __shfl_sync(0xffffffffu, uiv, t);
            // state updates (complex)
            float t0r = fmaf(na0i, s0i, ur);  t0r = fmaf(a0r, s0r, t0r);
            float t0i = fmaf(a0i,  s0r, ui);  t0i = fmaf(a0r, s0i, t0i);
            float t1r = fmaf(na1i, s1i, ur);  t1r = fmaf(a1r, s1r, t1r);
            float t1i = fmaf(a1i,  s1r, ui);  t1i = fmaf(a1r, s1i, t1i);
            s0r = t0r; s0i = t0i; s1r = t1r; s1i = t1i;
            // partial output: w · s (complex)
            float pr = w0r * s0r;
            pr = fmaf(nw0i, s0i, pr);
            pr = fmaf(w1r,  s1r, pr);
            pr = fmaf(nw1i, s1i, pr);
            float pi = w0r * s0i;
            pi = fmaf(w0i, s0r, pi);
            pi = fmaf(w1r, s1i, pi);
            pi = fmaf(w1i, s1r, pi);
            // warp reduction over all 64 states
#pragma unroll
            for (int off = 16; off > 0; off >>= 1) {
                pr += __shfl_xor_sync(0xffffffffu, pr, off);
                pi += __shfl_xor_sync(0xffffffffu, pi, off);
            }
            if (t == lane) { kr = pr; ki = pi; }
        }
        yre[l0 + lane] = kr;   // coalesced
        yim[l0 + lane] = ki;
    }
}

// ======================= 5) GEMM2: out = y @ Wout =======================
// A[m,k] = d_bufA[b*D*L + k*L + l]  (y transposed, re rows 0..511, im rows 512..1023)
__global__ __launch_bounds__(256) void k_gemm2(const float* __restrict__ W,
                                               float* __restrict__ Out) {
    __shared__ float As[8][128];
    __shared__ float Bs[8][128];
    const int K = DD;
    int tid = threadIdx.x;
    int m0 = blockIdx.y * 128;
    int n0 = blockIdx.x * 128;
    int b  = m0 >> 11;             // tiles never cross batch boundary
    int l0 = m0 & (LL - 1);

    int a_k = tid >> 5;            // 0..7
    int a_m = (tid & 31) * 4;      // 0..124
    int b_k = tid >> 5;
    int b_n = (tid & 31) * 4;

    const float* Ap = d_bufA + (size_t)b * DD * LL + (size_t)a_k * LL + l0 + a_m;
    const float* Bp = W + (size_t)b_k * DD + n0 + b_n;

    int tmb = (tid >> 4) * 8;
    int tnb = (tid & 15) * 8;

    unsigned long long acc[8][4];
#pragma unroll
    for (int i = 0; i < 8; i++)
#pragma unroll
        for (int j = 0; j < 4; j++) acc[i][j] = 0ull;

    float4 av = *(const float4*)Ap;
    float4 bv = *(const float4*)Bp;

    for (int kt = 0; kt < K; kt += 8) {
        __syncthreads();
        *(float4*)&As[a_k][a_m] = av;
        *(float4*)&Bs[b_k][b_n] = bv;
        __syncthreads();
        if (kt + 8 < K) {
            av = *(const float4*)(Ap + (size_t)(kt + 8) * LL);
            bv = *(const float4*)(Bp + (size_t)(kt + 8) * DD);
        }
#pragma unroll
        for (int kk = 0; kk < 8; kk++) {
            float4 x0 = *(const float4*)&As[kk][tmb];
            float4 x1 = *(const float4*)&As[kk][tmb + 4];
            float4 y0 = *(const float4*)&Bs[kk][tnb];
            float4 y1 = *(const float4*)&Bs[kk][tnb + 4];
            unsigned long long bp0 = pack2(y0.x, y0.y);
            unsigned long long bp1 = pack2(y0.z, y0.w);
            unsigned long long bp2 = pack2(y1.x, y1.y);
            unsigned long long bp3 = pack2(y1.z, y1.w);
            float aa[8] = {x0.x, x0.y, x0.z, x0.w, x1.x, x1.y, x1.z, x1.w};
#pragma unroll
            for (int i = 0; i < 8; i++) {
                unsigned long long ad = pack2(aa[i], aa[i]);
                fma2(acc[i][0], ad, bp0);
                fma2(acc[i][1], ad, bp1);
                fma2(acc[i][2], ad, bp2);
                fma2(acc[i][3], ad, bp3);
            }
        }
    }
#pragma unroll
    for (int i = 0; i < 8; i++) {
        size_t off = (size_t)(m0 + tmb + i) * DD + n0 + tnb;
        float4 o0, o1;
        o0.x = lo32(acc[i][0]);  o0.y = hi32(acc[i][0]);
        o0.z = lo32(acc[i][1]);  o0.w = hi32(acc[i][1]);
        o1.x = lo32(acc[i][2]);  o1.y = hi32(acc[i][2]);
        o1.z = lo32(acc[i][3]);  o1.w = hi32(acc[i][3]);
        *(float4*)&Out[off]     = o0;
        *(float4*)&Out[off + 4] = o1;
    }
}

// ======================= launch =======================
extern "C" void kernel_launch(void* const* d_in, const int* in_sizes, int n_in,
                              void* d_out, int out_size) {
    (void)in_sizes; (void)n_in; (void)out_size;
    const float* x    = (const float*)d_in[0];
    const float* g    = (const float*)d_in[1];
    const float* w_in = (const float*)d_in[2];
    const float* ck   = (const float*)d_in[3];
    const float* cb   = (const float*)d_in[4];
    const float* logd = (const float*)d_in[5];
    const float* freq = (const float*)d_in[6];
    const float* wre  = (const float*)d_in[7];
    const float* wim  = (const float*)d_in[8];
    const float* wout = (const float*)d_in[9];
    float* out = (float*)d_out;

    k_params<<<(HH * NN + 255) / 256, 256>>>(logd, freq, wre, wim);
    k_conv<<<(TOT + 255) / 256, 256>>>(g, ck, cb);

    dim3 gg(DD / 128, (NB * LL) / 128);   // (8, 128)
    k_gemm1<<<gg, 256>>>(x, w_in);

    dim3 gt(DD / 32, LL / 32, NB);        // (32, 64, 8)
    k_transpose<<<gt, dim3(32, 8)>>>();

    k_scan<<<512, 256>>>();               // 4096 warps = one per (b,h)

    k_gemm2<<<gg, 256>>>(wout, out);
}

// round 17
// speedup vs baseline: 1.6200x; 1.6200x over previous
#include <cuda_runtime.h>
#include <math.h>

// Problem constants
#define NB   8
#define LL   2048
#define DD   1024
#define HH   512
#define NN   64
#define KSZ  4
#define TOT  (NB*LL*DD)   // 16,777,216 elements = 64 MiB fp32

// -------- device scratch (no runtime allocation allowed) --------
static __device__ float  d_bufA[TOT];   // g_act (B,L,D); later reused as y_t (B,D,L)
static __device__ float  d_bufB[TOT];   // u (B,L,D)
static __device__ float  d_bufC[TOT];   // u_t (B,D,L)
static __device__ float4 d_par[HH*NN];  // (a_re, a_im, w_re, w_im) per (h,n)

// -------- packed f32x2 helpers (FFMA2 path, PTX-only on sm_103a) --------
__device__ __forceinline__ unsigned long long pack2(float lo, float hi) {
    unsigned long long r;
    asm("mov.b64 %0, {%1, %2};" : "=l"(r) : "f"(lo), "f"(hi));
    return r;
}
__device__ __forceinline__ void fma2(unsigned long long& d,
                                     unsigned long long a,
                                     unsigned long long b) {
    asm("fma.rn.f32x2 %0, %1, %2, %0;" : "+l"(d) : "l"(a), "l"(b));
}
__device__ __forceinline__ float lo32(unsigned long long v) {
    return __uint_as_float((unsigned)(v & 0xffffffffull));
}
__device__ __forceinline__ float hi32(unsigned long long v) {
    return __uint_as_float((unsigned)(v >> 32));
}

// ======================= 0) SSM parameter precompute =======================
// A = -exp(log_decay) + i*freq ; step multiplier a = exp(A) ; w = w_re + i*w_im
__global__ void k_params(const float* __restrict__ logd,
                         const float* __restrict__ freq,
                         const float* __restrict__ wre,
                         const float* __restrict__ wim) {
    int i = blockIdx.x * blockDim.x + threadIdx.x;
    if (i >= HH * NN) return;
    float mag = expf(-expf(logd[i]));   // |a| = exp(-exp(log_decay)) < 1
    float s, c;
    sincosf(freq[i], &s, &c);
    d_par[i] = make_float4(mag * c, mag * s, wre[i], wim[i]);
}

// ======================= 1) depthwise circular conv + SiLU =======================
// pad: pb=1, pa=2 (CIRCULAR). out[b,l,d] = silu( sum_k g[b,(l+k-1)%L,d]*ker[k,0,d] + bias[d] )
__global__ void k_conv(const float* __restrict__ g,
                       const float* __restrict__ ker,
                       const float* __restrict__ bias) {
    int idx = blockIdx.x * blockDim.x + threadIdx.x;
    if (idx >= TOT) return;
    int d = idx & (DD - 1);
    int l = (idx >> 10) & (LL - 1);
    int b = idx >> 21;
    const float* gb = g + (size_t)b * LL * DD;
    float acc = bias[d];
#pragma unroll
    for (int k = 0; k < KSZ; k++) {
        int ll = (l + k - 1 + LL) & (LL - 1);
        acc += gb[(size_t)ll * DD + d] * ker[k * DD + d];
    }
    float sg = 1.0f / (1.0f + expf(-acc));   // silu = x * sigmoid(x)
    d_bufA[idx] = acc * sg;
}

// ======================= 2) GEMM1: u = (X @ Win) * g_act =======================
// X: (16384,1024) row-major ; Win: (1024,1024) row-major ; out -> d_bufB (B,L,D)
__global__ __launch_bounds__(256) void k_gemm1(const float* __restrict__ X,
                                               const float* __restrict__ W) {
    __shared__ float As[8][128];
    __shared__ float Bs[8][128];
    const int K = DD;
    int tid = threadIdx.x;
    int m0 = blockIdx.y * 128;
    int n0 = blockIdx.x * 128;

    int a_m = tid >> 1;            // 0..127
    int a_k = (tid & 1) * 4;       // 0 or 4
    int b_k = tid >> 5;            // 0..7
    int b_n = (tid & 31) * 4;      // 0..124

    const float* Ap = X + (size_t)(m0 + a_m) * K + a_k;
    const float* Bp = W + (size_t)b_k * DD + n0 + b_n;

    int tmb = (tid >> 4) * 8;      // row offset within tile
    int tnb = (tid & 15) * 8;      // col offset within tile

    unsigned long long acc[8][4];
#pragma unroll
    for (int i = 0; i < 8; i++)
#pragma unroll
        for (int j = 0; j < 4; j++) acc[i][j] = 0ull;

    float4 av = *(const float4*)Ap;
    float4 bv = *(const float4*)Bp;

    for (int kt = 0; kt < K; kt += 8) {
        __syncthreads();
        As[a_k + 0][a_m] = av.x;
        As[a_k + 1][a_m] = av.y;
        As[a_k + 2][a_m] = av.z;
        As[a_k + 3][a_m] = av.w;
        *(float4*)&Bs[b_k][b_n] = bv;
        __syncthreads();
        if (kt + 8 < K) {
            av = *(const float4*)(Ap + kt + 8);
            bv = *(const float4*)(Bp + (size_t)(kt + 8) * DD);
        }
#pragma unroll
        for (int kk = 0; kk < 8; kk++) {
            float4 x0 = *(const float4*)&As[kk][tmb];
            float4 x1 = *(const float4*)&As[kk][tmb + 4];
            float4 y0 = *(const float4*)&Bs[kk][tnb];
            float4 y1 = *(const float4*)&Bs[kk][tnb + 4];
            unsigned long long bp0 = pack2(y0.x, y0.y);
            unsigned long long bp1 = pack2(y0.z, y0.w);
            unsigned long long bp2 = pack2(y1.x, y1.y);
            unsigned long long bp3 = pack2(y1.z, y1.w);
            float aa[8] = {x0.x, x0.y, x0.z, x0.w, x1.x, x1.y, x1.z, x1.w};
#pragma unroll
            for (int i = 0; i < 8; i++) {
                unsigned long long ad = pack2(aa[i], aa[i]);
                fma2(acc[i][0], ad, bp0);
                fma2(acc[i][1], ad, bp1);
                fma2(acc[i][2], ad, bp2);
                fma2(acc[i][3], ad, bp3);
            }
        }
    }
    // epilogue: multiply by gate, write u
#pragma unroll
    for (int i = 0; i < 8; i++) {
        size_t off = (size_t)(m0 + tmb + i) * DD + n0 + tnb;
        float4 g0 = *(const float4*)&d_bufA[off];
        float4 g1 = *(const float4*)&d_bufA[off + 4];
        float4 o0, o1;
        o0.x = lo32(acc[i][0]) * g0.x;  o0.y = hi32(acc[i][0]) * g0.y;
        o0.z = lo32(acc[i][1]) * g0.z;  o0.w = hi32(acc[i][1]) * g0.w;
        o1.x = lo32(acc[i][2]) * g1.x;  o1.y = hi32(acc[i][2]) * g1.y;
        o1.z = lo32(acc[i][3]) * g1.z;  o1.w = hi32(acc[i][3]) * g1.w;
        *(float4*)&d_bufB[off]     = o0;
        *(float4*)&d_bufB[off + 4] = o1;
    }
}

// ======================= 3) transpose u: (B,L,D) -> (B,D,L) =======================
__global__ void k_transpose() {
    __shared__ float tile[32][33];
    int b  = blockIdx.z;
    int l0 = blockIdx.y * 32;
    int d0 = blockIdx.x * 32;
    int tx = threadIdx.x, ty = threadIdx.y;       // block (32,8)
    const float* src = d_bufB + (size_t)b * LL * DD;
    float*       dst = d_bufC + (size_t)b * LL * DD;
#pragma unroll
    for (int i = 0; i < 32; i += 8)
        tile[ty + i][tx] = src[(size_t)(l0 + ty + i) * DD + d0 + tx];
    __syncthreads();
#pragma unroll
    for (int i = 0; i < 32; i += 8)
        dst[(size_t)(d0 + ty + i) * LL + l0 + tx] = tile[tx][ty + i];
}

// ======================= 4) complex diagonal SSM scan =======================
// One warp per (b,h). Lane owns states n=lane and n=lane+32.
// S[l] = a*S[l-1] + u[l];  y[l] = sum_n w_n * S_n[l]  (exactly equals FFT conv)
__global__ __launch_bounds__(256) void k_scan() {
    int warp = (blockIdx.x * blockDim.x + threadIdx.x) >> 5;   // 0..4095
    int lane = threadIdx.x & 31;
    int b = warp >> 9;        // /512
    int h = warp & 511;

    const float* ure = d_bufC + ((size_t)b * DD + h) * LL;
    const float* uim = ure + (size_t)HH * LL;
    float* yre = d_bufA + ((size_t)b * DD + h) * LL;
    float* yim = yre + (size_t)HH * LL;

    float4 p0 = d_par[h * NN + lane];
    float4 p1 = d_par[h * NN + lane + 32];
    float a0r = p0.x, a0i = p0.y, w0r = p0.z, w0i = p0.w;
    float a1r = p1.x, a1i = p1.y, w1r = p1.z, w1i = p1.w;
    float na0i = -a0i, na1i = -a1i, nw0i = -w0i, nw1i = -w1i;

    float s0r = 0.f, s0i = 0.f, s1r = 0.f, s1i = 0.f;

    for (int l0 = 0; l0 < LL; l0 += 32) {
        float urv = ure[l0 + lane];
        float uiv = uim[l0 + lane];
        float kr = 0.f, ki = 0.f;
#pragma unroll
        for (int t = 0; t < 32; t++) {
            float ur = __shfl_sync(0xffffffffu, urv, t);
            float ui = __shfl_sync(0xffffffffu, uiv, t);
            // state updates (complex)
            float t0r = fmaf(na0i, s0i, ur);  t0r = fmaf(a0r, s0r, t0r);
            float t0i = fmaf(a0i,  s0r, ui);  t0i = fmaf(a0r, s0i, t0i);
            float t1r = fmaf(na1i, s1i, ur);  t1r = fmaf(a1r, s1r, t1r);
            float t1i = fmaf(a1i,  s1r, ui);  t1i = fmaf(a1r, s1i, t1i);
            s0r = t0r; s0i = t0i; s1r = t1r; s1i = t1i;
            // partial output: w · s (complex)
            float pr = w0r * s0r;
            pr = fmaf(nw0i, s0i, pr);
            pr = fmaf(w1r,  s1r, pr);
            pr = fmaf(nw1i, s1i, pr);
            float pi = w0r * s0i;
            pi = fmaf(w0i, s0r, pi);
            pi = fmaf(w1r, s1i, pi);
            pi = fmaf(w1i, s1r, pi);
            // warp reduction over all 64 states
#pragma unroll
            for (int off = 16; off > 0; off >>= 1) {
                pr += __shfl_xor_sync(0xffffffffu, pr, off);
                pi += __shfl_xor_sync(0xffffffffu, pi, off);
            }
            if (t == lane) { kr = pr; ki = pi; }
        }
        yre[l0 + lane] = kr;   // coalesced
        yim[l0 + lane] = ki;
    }
}

// ======================= 5) GEMM2: out = y @ Wout =======================
// A[m,k] = d_bufA[b*D*L + k*L + l]  (y transposed, re rows 0..511, im rows 512..1023)
__global__ __launch_bounds__(256) void k_gemm2(const float* __restrict__ W,
                                               float* __restrict__ Out) {
    __shared__ float As[8][128];
    __shared__ float Bs[8][128];
    const int K = DD;
    int tid = threadIdx.x;
    int m0 = blockIdx.y * 128;
    int n0 = blockIdx.x * 128;
    int b  = m0 >> 11;             // tiles never cross batch boundary
    int l0 = m0 & (LL - 1);

    int a_k = tid >> 5;            // 0..7
    int a_m = (tid & 31) * 4;      // 0..124
    int b_k = tid >> 5;
    int b_n = (tid & 31) * 4;

    const float* Ap = d_bufA + (size_t)b * DD * LL + (size_t)a_k * LL + l0 + a_m;
    const float* Bp = W + (size_t)b_k * DD + n0 + b_n;

    int tmb = (tid >> 4) * 8;
    int tnb = (tid & 15) * 8;

    unsigned long long acc[8][4];
#pragma unroll
    for (int i = 0; i < 8; i++)
#pragma unroll
        for (int j = 0; j < 4; j++) acc[i][j] = 0ull;

    float4 av = *(const float4*)Ap;
    float4 bv = *(const float4*)Bp;

    for (int kt = 0; kt < K; kt += 8) {
        __syncthreads();
        *(float4*)&As[a_k][a_m] = av;
        *(float4*)&Bs[b_k][b_n] = bv;
        __syncthreads();
        if (kt + 8 < K) {
            av = *(const float4*)(Ap + (size_t)(kt + 8) * LL);
            bv = *(const float4*)(Bp + (size_t)(kt + 8) * DD);
        }
#pragma unroll
        for (int kk = 0; kk < 8; kk++) {
            float4 x0 = *(const float4*)&As[kk][tmb];
            float4 x1 = *(const float4*)&As[kk][tmb + 4];
            float4 y0 = *(const float4*)&Bs[kk][tnb];
            float4 y1 = *(const float4*)&Bs[kk][tnb + 4];
            unsigned long long bp0 = pack2(y0.x, y0.y);
            unsigned long long bp1 = pack2(y0.z, y0.w);
            unsigned long long bp2 = pack2(y1.x, y1.y);
            unsigned long long bp3 = pack2(y1.z, y1.w);
            float aa[8] = {x0.x, x0.y, x0.z, x0.w, x1.x, x1.y, x1.z, x1.w};
#pragma unroll
            for (int i = 0; i < 8; i++) {
                unsigned long long ad = pack2(aa[i], aa[i]);
                fma2(acc[i][0], ad, bp0);
                fma2(acc[i][1], ad, bp1);
                fma2(acc[i][2], ad, bp2);
                fma2(acc[i][3], ad, bp3);
            }
        }
    }
#pragma unroll
    for (int i = 0; i < 8; i++) {
        size_t off = (size_t)(m0 + tmb + i) * DD + n0 + tnb;
        float4 o0, o1;
        o0.x = lo32(acc[i][0]);  o0.y = hi32(acc[i][0]);
        o0.z = lo32(acc[i][1]);  o0.w = hi32(acc[i][1]);
        o1.x = lo32(acc[i][2]);  o1.y = hi32(acc[i][2]);
        o1.z = lo32(acc[i][3]);  o1.w = hi32(acc[i][3]);
        *(float4*)&Out[off]     = o0;
        *(float4*)&Out[off + 4] = o1;
    }
}

// ======================= launch =======================
extern "C" void kernel_launch(void* const* d_in, const int* in_sizes, int n_in,
                              void* d_out, int out_size) {
    (void)in_sizes; (void)n_in; (void)out_size;
    const float* x    = (const float*)d_in[0];
    const float* g    = (const float*)d_in[1];
    const float* w_in = (const float*)d_in[2];
    const float* ck   = (const float*)d_in[3];
    const float* cb   = (const float*)d_in[4];
    const float* logd = (const float*)d_in[5];
    const float* freq = (const float*)d_in[6];
    const float* wre  = (const float*)d_in[7];
    const float* wim  = (const float*)d_in[8];
    const float* wout = (const float*)d_in[9];
    float* out = (float*)d_out;

    k_params<<<(HH * NN + 255) / 256, 256>>>(logd, freq, wre, wim);
    k_conv<<<(TOT + 255) / 256, 256>>>(g, ck, cb);

    dim3 gg(DD / 128, (NB * LL) / 128);   // (8, 128)
    k_gemm1<<<gg, 256>>>(x, w_in);

    dim3 gt(DD / 32, LL / 32, NB);        // (32, 64, 8)
    k_transpose<<<gt, dim3(32, 8)>>>();

    k_scan<<<512, 256>>>();               // 4096 warps = one per (b,h)

    k_gemm2<<<gg, 256>>>(wout, out);
}